// round 15
// baseline (speedup 1.0000x reference)
#include <cuda_runtime.h>

// RNN_26895085207932 : Elman RNN, SEQ=2048, B=4096, IN=1, H=32 + Linear(32->1)
// R14: R12 base (champion structure, 2048 warps) + asymmetric chain schedule:
// shuffle-feeding chains D,C issue in the FIRST half of the fma window (their
// shuffles fly early); B is split into two 4-deep sub-chains (+1 add2) and
// interleaved with A in the second half so its shuffle merges ~20cyc before A
// completes. Removes most of the exposed last-shuffle latency per step.

typedef unsigned long long ull;

static constexpr int SEQ = 2048;
static constexpr int B   = 4096;
static constexpr int H   = 32;
static constexpr int ROWF2 = 34;             // ring row stride in float2 (2 pad)
static constexpr int ROWB  = ROWF2 * 8;      // 272 bytes; 16B-aligned rows

__device__ __forceinline__ ull pack2(float lo, float hi) {
    ull r; asm("mov.b64 %0, {%1, %2};" : "=l"(r) : "f"(lo), "f"(hi)); return r;
}
__device__ __forceinline__ void unpack2(ull v, float& lo, float& hi) {
    asm("mov.b64 {%0, %1}, %2;" : "=f"(lo), "=f"(hi) : "l"(v));
}
__device__ __forceinline__ ull fma2(ull a, ull b, ull c) {
    ull d; asm("fma.rn.f32x2 %0, %1, %2, %3;" : "=l"(d) : "l"(a), "l"(b), "l"(c)); return d;
}
__device__ __forceinline__ ull add2(ull a, ull b) {
    ull d; asm("add.rn.f32x2 %0, %1, %2;" : "=l"(d) : "l"(a), "l"(b)); return d;
}
__device__ __forceinline__ ull mul2(ull a, ull b) {
    ull d; asm("mul.rn.f32x2 %0, %1, %2;" : "=l"(d) : "l"(a), "l"(b)); return d;
}
__device__ __forceinline__ ull shfl_xor2(ull v, int d) {
    unsigned lo = (unsigned)v, hi = (unsigned)(v >> 32);
    lo = __shfl_xor_sync(0xffffffffu, lo, d);
    hi = __shfl_xor_sync(0xffffffffu, hi, d);
    return ((ull)hi << 32) | (ull)lo;
}
__device__ __forceinline__ float tanh_fast(float z) {
    float r; asm("tanh.approx.f32 %0, %1;" : "=f"(r) : "f"(z)); return r;
}
__device__ __forceinline__ void sts64(ull v, const void* p) {
    asm volatile("st.shared.b64 [%0], %1;"
                 :: "l"(__cvta_generic_to_shared(p)), "l"(v) : "memory");
}
__device__ __forceinline__ float guard_scale(float w) {
    float a = fabsf(w);
    return (a < 1e-6f) ? copysignf(1e-6f, w) : w;
}

// One RNN step. Chain order: D,C first (shuffles fly early), then B split
// into two 4-deep halves interleaved with A (seeded 8-deep). Final grouping
// matches R12: z = (pA + rB) + (rC + rD).
#define RNN_STEP(ST, CHECKED)                                                 \
    {                                                                         \
        const int st_ = (ST);                                                 \
        const int u_  = st_ & 3;                                              \
        float2 xs = xpipe[u_];                                                \
        if (!(CHECKED) || (st_ + 4 < SEQ))                                    \
            xpipe[u_] = xnext[(size_t)st_ * (B / 2)];                         \
                                                                              \
        ulonglong2 hv0 = rdq[0];                                              \
        ulonglong2 hv1 = rdq[1];                                              \
        ulonglong2 hv2 = rdq[2];                                              \
        ulonglong2 hv3 = rdq[3];                                              \
                                                                              \
        /* ---- phase 1: D and C chains (8-deep each, interleaved) ---- */    \
        ull pD = fma2(hv0.x, wd[0], mul2(hv0.y, wd[1]));                      \
        ull pC = fma2(hv0.x, wc[0], mul2(hv0.y, wc[1]));                      \
        pD = fma2(hv1.x, wd[2], pD);                                          \
        pC = fma2(hv1.x, wc[2], pC);                                          \
        pD = fma2(hv1.y, wd[3], pD);                                          \
        pC = fma2(hv1.y, wc[3], pC);                                          \
        pD = fma2(hv2.x, wd[4], pD);                                          \
        pC = fma2(hv2.x, wc[4], pC);                                          \
        pD = fma2(hv2.y, wd[5], pD);                                          \
        pC = fma2(hv2.y, wc[5], pC);                                          \
        pD = fma2(hv3.x, wd[6], pD);                                          \
        pC = fma2(hv3.x, wc[6], pC);                                          \
        pD = fma2(hv3.y, wd[7], pD);                                          \
        pC = fma2(hv3.y, wc[7], pC);                                          \
        ull r3 = shfl_xor2(pD, 24);   /* in flight during phase 2 */          \
        ull r2 = shfl_xor2(pC, 16);                                           \
                                                                              \
        /* ---- phase 2: B split (2x4-deep) + A (seeded) interleaved ---- */  \
        ull pB0 = fma2(hv0.x, wb[0], mul2(hv0.y, wb[1]));                     \
        ull pB1 = fma2(hv2.x, wb[4], mul2(hv2.y, wb[5]));                     \
        ull pA  = fma2(pack2(xs.x, xs.y), wih2, bias2);                       \
        pB0 = fma2(hv1.x, wb[2], pB0);                                        \
        pB1 = fma2(hv3.x, wb[6], pB1);                                        \
        pA  = fma2(hv0.x, wa[0], pA);                                         \
        pB0 = fma2(hv1.y, wb[3], pB0);                                        \
        pB1 = fma2(hv3.y, wb[7], pB1);                                        \
        pA  = fma2(hv0.y, wa[1], pA);                                         \
        ull pB = add2(pB0, pB1);                                              \
        ull r1 = shfl_xor2(pB, 8);    /* hidden under A's tail */             \
        pA = fma2(hv1.x, wa[2], pA);                                          \
        pA = fma2(hv1.y, wa[3], pA);                                          \
        pA = fma2(hv2.x, wa[4], pA);                                          \
        pA = fma2(hv2.y, wa[5], pA);                                          \
        pA = fma2(hv3.x, wa[6], pA);                                          \
        pA = fma2(hv3.y, wa[7], pA);                                          \
                                                                              \
        ull z = add2(add2(pA, r1), add2(r2, r3));                             \
                                                                              \
        float zA_, zB_;                                                       \
        unpack2(z, zA_, zB_);                                                 \
        const ull h2_ = pack2(tanh_fast(zA_), tanh_fast(zB_));                \
                                                                              \
        sts64(mul2(h2_, sfc2), wrp);                                          \
        rdq = reinterpret_cast<const ulonglong2*>(wrp + dqs);                 \
        wrp += ROWB;                                                          \
    }

__global__ void __launch_bounds__(32, 14)
rnn_kernel(const float* __restrict__ x,      // (SEQ, B, 1)
           const float* __restrict__ hidden, // (1, B, H)
           const float* __restrict__ Wih,    // (H, 1)
           const float* __restrict__ bih,    // (H)
           const float* __restrict__ Whh,    // (H, H)
           const float* __restrict__ bhh,    // (H)
           const float* __restrict__ Wfc,    // (1, H)
           const float* __restrict__ bfc,    // (1)
           float* __restrict__ out)          // (SEQ, B, 1)
{
    __shared__ __align__(16) float2 ring[32][ROWF2];  // s*h per 32-step block

    const int j = threadIdx.x;
    const int q = j >> 3;                // k-quarter this lane reads
    const int g = j & 7;                 // quartet group
    const int myu = 4 * g + q;           // unit this lane owns
    const int ub  = 4 * g + (q ^ 1);     // unit of lane j^8
    const int uc  = 4 * g + (q ^ 2);     // unit of lane j^16
    const int ud  = 4 * g + (q ^ 3);     // unit of lane j^24
    const int kofs = 8 * q;

    const int bx = blockIdx.x;           // batch pair
    const int b0 = bx * 2;

    // Pre-divided weights: w'[u][k] = Whh[u][k] / s_k (s = guarded Wfc).
    ull wa[8], wb[8], wc[8], wd[8];
#pragma unroll
    for (int k = 0; k < 8; k++) {
        float inv = 1.0f / guard_scale(Wfc[kofs + k]);
        float a = Whh[myu * H + kofs + k] * inv;
        float b = Whh[ub  * H + kofs + k] * inv;
        float c = Whh[uc  * H + kofs + k] * inv;
        float d = Whh[ud  * H + kofs + k] * inv;
        wa[k] = pack2(a, a);
        wb[k] = pack2(b, b);
        wc[k] = pack2(c, c);
        wd[k] = pack2(d, d);
    }
    const float wih  = Wih[myu];
    const float bias = bih[myu] + bhh[myu];
    const ull wih2   = pack2(wih, wih);
    const ull bias2  = pack2(bias, bias);
    const float sfc  = guard_scale(Wfc[myu]);
    const ull sfc2   = pack2(sfc, sfc);
    const float bfc0 = bfc[0];

    // Initial state in row 31 (step 0 reads it).
    ring[31][myu] = make_float2(sfc * hidden[(size_t)b0 * H + myu],
                                sfc * hidden[(size_t)(b0 + 1) * H + myu]);
    __syncwarp();

    const float2* xg = reinterpret_cast<const float2*>(x) + bx;   // step stride B/2
    float2* og       = reinterpret_cast<float2*>(out) + bx;

    const int dqs = (8 * q - myu) * 8;   // write slot -> next read-quarter base
    char* const ring0 = reinterpret_cast<char*>(&ring[0][0]);
    const ulonglong2* rdq;
    char* wrp;

    float2 xpipe[4];
#pragma unroll
    for (int i = 0; i < 4; i++) xpipe[i] = xg[(size_t)i * (B / 2)];
    const float2* xnext = xg + 4 * (size_t)(B / 2);

    for (int base = 0; base < SEQ; base += 32) {
        rdq = reinterpret_cast<const ulonglong2*>(ring0 + 31 * ROWB + 8 * q * 8);
        wrp = ring0 + myu * 8;

        if (base + 32 < SEQ) {
#pragma unroll 2
            for (int qq = 0; qq < 8; qq++) {
                const int s4 = base + qq * 4;
                RNN_STEP(s4 + 0, false)
                RNN_STEP(s4 + 1, false)
                RNN_STEP(s4 + 2, false)
                RNN_STEP(s4 + 3, false)
            }
        } else {
#pragma unroll 1
            for (int qq = 0; qq < 8; qq++) {
                const int s4 = base + qq * 4;
                RNN_STEP(s4 + 0, true)
                RNN_STEP(s4 + 1, true)
                RNN_STEP(s4 + 2, true)
                RNN_STEP(s4 + 3, true)
            }
        }

        // Output reduction: lane j sums row j (timestep base+j), + bfc.
        {
            const ulonglong2* pr = reinterpret_cast<const ulonglong2*>(&ring[j][0]);
            ull s0 = 0, s1 = 0, s2 = 0, s3 = 0;
#pragma unroll
            for (int g2 = 0; g2 < 8; g2++) {
                ulonglong2 a = pr[2 * g2];
                ulonglong2 b = pr[2 * g2 + 1];
                s0 = add2(s0, a.x); s1 = add2(s1, a.y);
                s2 = add2(s2, b.x); s3 = add2(s3, b.y);
            }
            ull sv = add2(add2(s0, s1), add2(s2, s3));
            float oA, oB;
            unpack2(sv, oA, oB);
            og[(size_t)(base + j) * (B / 2)] = make_float2(oA + bfc0, oB + bfc0);
        }
    }
}

extern "C" void kernel_launch(void* const* d_in, const int* in_sizes, int n_in,
                              void* d_out, int out_size) {
    const float* x      = (const float*)d_in[0];
    const float* hidden = (const float*)d_in[1];
    const float* Wih    = (const float*)d_in[2];
    const float* bih    = (const float*)d_in[3];
    const float* Whh    = (const float*)d_in[4];
    const float* bhh    = (const float*)d_in[5];
    const float* Wfc    = (const float*)d_in[6];
    const float* bfc    = (const float*)d_in[7];
    (void)in_sizes; (void)n_in; (void)out_size;

    rnn_kernel<<<B / 2, 32>>>(x, hidden, Wih, bih, Whh, bhh, Wfc, bfc, (float*)d_out);
}

// round 16
// speedup vs baseline: 1.7021x; 1.7021x over previous
#include <cuda_runtime.h>

// RNN_26895085207932 : Elman RNN, SEQ=2048, B=4096, IN=1, H=32 + Linear(32->1)
// R15: R12 champion + interleaved-chunk ring layout. R12's matvec LDS.128 had
// 4 addresses at 64B stride (208B span -> 2 crossbar wavefronts each). New row
// layout stores 16B chunks round-robin across quarters (chunk c=k*4+q holds
// units 8q+2k..+1), so each LDS's 4 addresses sit in one 64B window -> 1 wf.
// Matvec LDS wavefronts 8 -> 4 per step; instruction count & math unchanged.

typedef unsigned long long ull;

static constexpr int SEQ = 2048;
static constexpr int B   = 4096;
static constexpr int H   = 32;
static constexpr int ROWB = 272;   // 256B data (16 chunks x 16B) + 16B pad

__device__ __forceinline__ ull pack2(float lo, float hi) {
    ull r; asm("mov.b64 %0, {%1, %2};" : "=l"(r) : "f"(lo), "f"(hi)); return r;
}
__device__ __forceinline__ void unpack2(ull v, float& lo, float& hi) {
    asm("mov.b64 {%0, %1}, %2;" : "=f"(lo), "=f"(hi) : "l"(v));
}
__device__ __forceinline__ ull fma2(ull a, ull b, ull c) {
    ull d; asm("fma.rn.f32x2 %0, %1, %2, %3;" : "=l"(d) : "l"(a), "l"(b), "l"(c)); return d;
}
__device__ __forceinline__ ull add2(ull a, ull b) {
    ull d; asm("add.rn.f32x2 %0, %1, %2;" : "=l"(d) : "l"(a), "l"(b)); return d;
}
__device__ __forceinline__ ull mul2(ull a, ull b) {
    ull d; asm("mul.rn.f32x2 %0, %1, %2;" : "=l"(d) : "l"(a), "l"(b)); return d;
}
__device__ __forceinline__ ull shfl_xor2(ull v, int d) {
    unsigned lo = (unsigned)v, hi = (unsigned)(v >> 32);
    lo = __shfl_xor_sync(0xffffffffu, lo, d);
    hi = __shfl_xor_sync(0xffffffffu, hi, d);
    return ((ull)hi << 32) | (ull)lo;
}
__device__ __forceinline__ float tanh_fast(float z) {
    float r; asm("tanh.approx.f32 %0, %1;" : "=f"(r) : "f"(z)); return r;
}
__device__ __forceinline__ void sts64(ull v, const void* p) {
    asm volatile("st.shared.b64 [%0], %1;"
                 :: "l"(__cvta_generic_to_shared(p)), "l"(v) : "memory");
}
__device__ __forceinline__ float guard_scale(float w) {
    float a = fabsf(w);
    return (a < 1e-6f) ? copysignf(1e-6f, w) : w;
}
// Byte offset of unit u's float2 slot within an interleaved row:
// chunk = ((u&7)>>1)*4 + (u>>3), half = u&1.
__device__ __forceinline__ int slotbyte(int u) {
    return ((((u & 7) >> 1) * 4 + (u >> 3)) * 16) + ((u & 1) * 8);
}

// One RNN step — identical math & ordering to R12; only the ring addressing
// changed (reads at ul2 stride 4 = 64B chunk stride).
#define RNN_STEP(ST, CHECKED)                                                 \
    {                                                                         \
        const int st_ = (ST);                                                 \
        const int u_  = st_ & 3;                                              \
        float2 xs = xpipe[u_];                                                \
        if (!(CHECKED) || (st_ + 4 < SEQ))                                    \
            xpipe[u_] = xnext[(size_t)st_ * (B / 2)];                         \
                                                                              \
        const ulonglong2* hq_ = rdq;                                          \
        ull pA = fma2(pack2(xs.x, xs.y), wih2, bias2);                        \
        ull pB = 0, pC = 0, pD = 0;                                           \
        _Pragma("unroll")                                                     \
        for (int kk = 0; kk < 4; kk++) {                                      \
            ulonglong2 hv = hq_[4 * kk];                                      \
            pA = fma2(hv.x, wa[2 * kk],     pA);                              \
            pB = fma2(hv.x, wb[2 * kk],     pB);                              \
            pC = fma2(hv.x, wc[2 * kk],     pC);                              \
            pD = fma2(hv.x, wd[2 * kk],     pD);                              \
            pA = fma2(hv.y, wa[2 * kk + 1], pA);                              \
            pB = fma2(hv.y, wb[2 * kk + 1], pB);                              \
            pC = fma2(hv.y, wc[2 * kk + 1], pC);                              \
            pD = fma2(hv.y, wd[2 * kk + 1], pD);                              \
        }                                                                     \
                                                                              \
        ull r1 = shfl_xor2(pB, 8);                                            \
        ull r2 = shfl_xor2(pC, 16);                                           \
        ull r3 = shfl_xor2(pD, 24);                                           \
        ull z  = add2(add2(pA, r1), add2(r2, r3));                            \
                                                                              \
        float zA_, zB_;                                                       \
        unpack2(z, zA_, zB_);                                                 \
        const ull h2_ = pack2(tanh_fast(zA_), tanh_fast(zB_));                \
                                                                              \
        sts64(mul2(h2_, sfc2), wrp);                                          \
        rdq = reinterpret_cast<const ulonglong2*>(wrp + dqs);                 \
        wrp += ROWB;                                                          \
    }

__global__ void __launch_bounds__(32, 14)
rnn_kernel(const float* __restrict__ x,      // (SEQ, B, 1)
           const float* __restrict__ hidden, // (1, B, H)
           const float* __restrict__ Wih,    // (H, 1)
           const float* __restrict__ bih,    // (H)
           const float* __restrict__ Whh,    // (H, H)
           const float* __restrict__ bhh,    // (H)
           const float* __restrict__ Wfc,    // (1, H)
           const float* __restrict__ bfc,    // (1)
           float* __restrict__ out)          // (SEQ, B, 1)
{
    // ring[r] = interleaved row of s*h for timestep (blockbase + r).
    __shared__ __align__(16) float2 ring[32][ROWB / 8];

    const int j = threadIdx.x;
    const int q = j >> 3;                // k-quarter this lane reads
    const int g = j & 7;                 // quartet group
    const int myu = 4 * g + q;           // unit this lane owns
    const int ub  = 4 * g + (q ^ 1);     // unit of lane j^8
    const int uc  = 4 * g + (q ^ 2);     // unit of lane j^16
    const int ud  = 4 * g + (q ^ 3);     // unit of lane j^24
    const int kofs = 8 * q;

    const int bx = blockIdx.x;           // batch pair
    const int b0 = bx * 2;

    // Pre-divided weights: w'[u][k] = Whh[u][k] / s_k (s = guarded Wfc).
    // Read-index mapping is unchanged: LDS chunk kk yields units kofs+2kk,+1.
    ull wa[8], wb[8], wc[8], wd[8];
#pragma unroll
    for (int k = 0; k < 8; k++) {
        float inv = 1.0f / guard_scale(Wfc[kofs + k]);
        float a = Whh[myu * H + kofs + k] * inv;
        float b = Whh[ub  * H + kofs + k] * inv;
        float c = Whh[uc  * H + kofs + k] * inv;
        float d = Whh[ud  * H + kofs + k] * inv;
        wa[k] = pack2(a, a);
        wb[k] = pack2(b, b);
        wc[k] = pack2(c, c);
        wd[k] = pack2(d, d);
    }
    const float wih  = Wih[myu];
    const float bias = bih[myu] + bhh[myu];
    const ull wih2   = pack2(wih, wih);
    const ull bias2  = pack2(bias, bias);
    const float sfc  = guard_scale(Wfc[myu]);
    const ull sfc2   = pack2(sfc, sfc);
    const float bfc0 = bfc[0];

    char* const ring0 = reinterpret_cast<char*>(&ring[0][0]);
    const int myslot = slotbyte(myu);

    // Initial state into row 31 (step 0 reads it).
    *reinterpret_cast<float2*>(ring0 + 31 * ROWB + myslot) =
        make_float2(sfc * hidden[(size_t)b0 * H + myu],
                    sfc * hidden[(size_t)(b0 + 1) * H + myu]);
    __syncwarp();

    const float2* xg = reinterpret_cast<const float2*>(x) + bx;   // step stride B/2
    float2* og       = reinterpret_cast<float2*>(out) + bx;

    // write slot -> same row's read base (chunk q at byte q*16)
    const int dqs = q * 16 - myslot;
    const ulonglong2* rdq;
    char* wrp;

    float2 xpipe[4];
#pragma unroll
    for (int i = 0; i < 4; i++) xpipe[i] = xg[(size_t)i * (B / 2)];
    const float2* xnext = xg + 4 * (size_t)(B / 2);

    for (int base = 0; base < SEQ; base += 32) {
        rdq = reinterpret_cast<const ulonglong2*>(ring0 + 31 * ROWB + q * 16);
        wrp = ring0 + myslot;

        if (base + 32 < SEQ) {
#pragma unroll 2
            for (int qq = 0; qq < 8; qq++) {
                const int s4 = base + qq * 4;
                RNN_STEP(s4 + 0, false)
                RNN_STEP(s4 + 1, false)
                RNN_STEP(s4 + 2, false)
                RNN_STEP(s4 + 3, false)
            }
        } else {
#pragma unroll 1
            for (int qq = 0; qq < 8; qq++) {
                const int s4 = base + qq * 4;
                RNN_STEP(s4 + 0, true)
                RNN_STEP(s4 + 1, true)
                RNN_STEP(s4 + 2, true)
                RNN_STEP(s4 + 3, true)
            }
        }

        // Output reduction: lane j sums row j (timestep base+j) — 16 ul2 of
        // 256B data (unit order permuted by the chunk layout; sum over all 32
        // units is unchanged up to fp reassociation).
        {
            const ulonglong2* pr =
                reinterpret_cast<const ulonglong2*>(ring0 + j * ROWB);
            ull s0 = 0, s1 = 0, s2 = 0, s3 = 0;
#pragma unroll
            for (int g2 = 0; g2 < 8; g2++) {
                ulonglong2 a = pr[2 * g2];
                ulonglong2 b = pr[2 * g2 + 1];
                s0 = add2(s0, a.x); s1 = add2(s1, a.y);
                s2 = add2(s2, b.x); s3 = add2(s3, b.y);
            }
            ull sv = add2(add2(s0, s1), add2(s2, s3));
            float oA, oB;
            unpack2(sv, oA, oB);
            og[(size_t)(base + j) * (B / 2)] = make_float2(oA + bfc0, oB + bfc0);
        }
    }
}

extern "C" void kernel_launch(void* const* d_in, const int* in_sizes, int n_in,
                              void* d_out, int out_size) {
    const float* x      = (const float*)d_in[0];
    const float* hidden = (const float*)d_in[1];
    const float* Wih    = (const float*)d_in[2];
    const float* bih    = (const float*)d_in[3];
    const float* Whh    = (const float*)d_in[4];
    const float* bhh    = (const float*)d_in[5];
    const float* Wfc    = (const float*)d_in[6];
    const float* bfc    = (const float*)d_in[7];
    (void)in_sizes; (void)n_in; (void)out_size;

    rnn_kernel<<<B / 2, 32>>>(x, hidden, Wih, bih, Whh, bhh, Wfc, bfc, (float*)d_out);
}